// round 17
// baseline (speedup 1.0000x reference)
#include <cuda_runtime.h>
#include <cstdint>

// ---------------------------------------------------------------------------
// 2-layer LSTM (B=128, T=512, I=64, H=512) + head (C=3).
// Persistent kernel, 128 CTAs x 256 threads, 1 grid barrier per timestep.
// KEY CHANGE vs R4: recurrent state stored TRANSPOSED [k][b] so h loads are
// coalesced (1 line/warp instead of 8); math batch-packed in f32x2 with
// weights pre-duplicated (w,w) in SMEM. x pre-transposed by a helper kernel.
// ---------------------------------------------------------------------------

static constexpr int NB   = 128;
static constexpr int NT   = 512;
static constexpr int NI   = 64;
static constexpr int NH   = 512;
static constexpr int NC   = 3;
static constexpr int NCTA = 128;
static constexpr int NTHR = 256;
static constexpr int PD0  = (NI + NH) * 2 + 4;   // 1156 floats/row (dup + pad)
static constexpr int PD1  = (2 * NH) * 2 + 4;    // 2052 floats/row

__device__ __align__(16) float g_xT[(size_t)NT * NI * NB];   // [t][i][b]
__device__ __align__(16) float g_hAT[2][NH * NB];            // [buf][k][b]
__device__ __align__(16) float g_hBT[2][NH * NB];
__device__ unsigned g_cnt = 0;
__device__ unsigned g_gen = 0;

using u64 = unsigned long long;

__device__ __forceinline__ u64 ffma2(u64 a, u64 b, u64 c) {
    u64 d;
    asm("fma.rn.f32x2 %0, %1, %2, %3;" : "=l"(d) : "l"(a), "l"(b), "l"(c));
    return d;
}
__device__ __forceinline__ u64 ld64(const float* p) {
    return *reinterpret_cast<const u64*>(p);
}
__device__ __forceinline__ float lof(u64 v) {
    return __uint_as_float((unsigned)(v & 0xffffffffu));
}
__device__ __forceinline__ float hif(u64 v) {
    return __uint_as_float((unsigned)(v >> 32));
}
__device__ __forceinline__ float sigm(float v) { return 1.0f / (1.0f + expf(-v)); }

__device__ __forceinline__ void grid_barrier(unsigned base, unsigned idx) {
    __syncthreads();
    if (threadIdx.x == 0) {
        __threadfence();
        if (atomicAdd(&g_cnt, 1u) == NCTA - 1) {
            g_cnt = 0;
            __threadfence();
            atomicAdd(&g_gen, 1u);
        } else {
            volatile unsigned* vg = &g_gen;
            while ((unsigned)(*vg - base) < idx + 1u) __nanosleep(32);
            __threadfence();
        }
    }
    __syncthreads();
}

// ---- x transpose: [b][t][i] -> g_xT[t][i][b] ------------------------------
__global__ void transpose_x_kernel(const float* __restrict__ x) {
    __shared__ float tile[32][65];
    const int t  = blockIdx.x;
    const int b0 = blockIdx.y * 32;
    const int tid = threadIdx.x;
    for (int idx = tid; idx < 32 * 64; idx += 256) {
        int bb = idx >> 6, i = idx & 63;
        tile[bb][i] = x[((size_t)(b0 + bb) * NT + t) * NI + i];
    }
    __syncthreads();
    for (int idx = tid; idx < 32 * 64; idx += 256) {
        int i = idx >> 5, bb = idx & 31;
        g_xT[((size_t)t * NI + i) * NB + b0 + bb] = tile[bb][i];
    }
}

__global__ void __launch_bounds__(NTHR, 1)
lstm_persistent(const float* __restrict__ Wih0, const float* __restrict__ Whh0,
                const float* __restrict__ bih0, const float* __restrict__ bhh0,
                const float* __restrict__ Wih1, const float* __restrict__ Whh1,
                const float* __restrict__ bih1, const float* __restrict__ bhh1,
                const float* __restrict__ Wout, const float* __restrict__ bout,
                float* __restrict__ out) {
    extern __shared__ float smem[];
    float* sW0 = smem;                 // [16][PD0] duplicated (w,w) pairs
    float* sW1 = smem + 16 * PD0;      // [16][PD1]

    const int tid = threadIdx.x;
    const int cta = blockIdx.x;
    const int j0  = cta * 4;
    const int jl  = tid & 3;
    const int bg  = tid >> 2;          // 0..63
    const int b0  = bg * 2;            // this thread's 2 batches: b0, b0+1
    const int j   = j0 + jl;

    // ---- stage duplicated weight slices ----
    for (int r = 0; r < 16; r++) {
        int g = r >> 2, jj = r & 3;
        int rg = g * NH + j0 + jj;
        for (int c = tid; c < NI + NH; c += NTHR) {
            float w = (c < NI) ? Wih0[rg * NI + c] : Whh0[rg * NH + (c - NI)];
            sW0[r * PD0 + 2 * c + 0] = w;
            sW0[r * PD0 + 2 * c + 1] = w;
        }
        for (int c = tid; c < 2 * NH; c += NTHR) {
            float w = (c < NH) ? Wih1[rg * NH + c] : Whh1[rg * NH + (c - NH)];
            sW1[r * PD1 + 2 * c + 0] = w;
            sW1[r * PD1 + 2 * c + 1] = w;
        }
    }

    // ---- zero t=0 "previous" buffers (buffer 1) ----
    {
        int base = (cta * NTHR + tid) * 2;    // covers exactly NH*NB
        g_hAT[1][base + 0] = 0.0f;
        g_hAT[1][base + 1] = 0.0f;
        g_hBT[1][base + 0] = 0.0f;
        g_hBT[1][base + 1] = 0.0f;
    }

    // ---- fused biases ----
    float bi0[4], bi1[4];
    #pragma unroll
    for (int g = 0; g < 4; g++) {
        int rg = g * NH + j;
        bi0[g] = bih0[rg] + bhh0[rg];
        bi1[g] = bih1[rg] + bhh1[rg];
    }

    const ulonglong2* w0d[4];
    const ulonglong2* w1d[4];
    #pragma unroll
    for (int g = 0; g < 4; g++) {
        w0d[g] = reinterpret_cast<const ulonglong2*>(sW0 + (g * 4 + jl) * PD0);
        w1d[g] = reinterpret_cast<const ulonglong2*>(sW1 + (g * 4 + jl) * PD1);
    }

    unsigned bar_base = 0;
    if (tid == 0) bar_base = *(volatile unsigned*)&g_gen;
    unsigned bn = 0;

    grid_barrier(bar_base, bn++);   // weights + zeroed buffers visible

    float cA0 = 0.f, cA1 = 0.f, cB0 = 0.f, cB1 = 0.f;

    for (int t = 0; t < NT; t++) {
        const int p = t & 1;
        const int q = p ^ 1;

        // ============ layer 0: gates = [x_t | hA_prev] @ W0 ==============
        {
            u64 acc[4] = {0ull, 0ull, 0ull, 0ull};

            const float* px = g_xT + ((size_t)t * NI) * NB + b0;
            #pragma unroll 4
            for (int kk = 0; kk < NI / 2; kk++) {
                u64 h0 = ld64(px + (2 * kk) * NB);
                u64 h1 = ld64(px + (2 * kk + 1) * NB);
                #pragma unroll
                for (int g = 0; g < 4; g++) {
                    ulonglong2 w = w0d[g][kk];
                    acc[g] = ffma2(h0, w.x, acc[g]);
                    acc[g] = ffma2(h1, w.y, acc[g]);
                }
            }
            const float* ph = g_hAT[q] + b0;
            #pragma unroll 4
            for (int kk = 0; kk < NH / 2; kk++) {
                u64 h0 = ld64(ph + (2 * kk) * NB);
                u64 h1 = ld64(ph + (2 * kk + 1) * NB);
                #pragma unroll
                for (int g = 0; g < 4; g++) {
                    ulonglong2 w = w0d[g][(NI / 2) + kk];
                    acc[g] = ffma2(h0, w.x, acc[g]);
                    acc[g] = ffma2(h1, w.y, acc[g]);
                }
            }
            // batch b0 (lo halves)
            {
                float ig = sigm(lof(acc[0]) + bi0[0]);
                float fg = sigm(lof(acc[1]) + bi0[1]);
                float gg = tanhf(lof(acc[2]) + bi0[2]);
                float og = sigm(lof(acc[3]) + bi0[3]);
                cA0 = fg * cA0 + ig * gg;
                float h = og * tanhf(cA0);
                // batch b1 (hi halves)
                float ig1 = sigm(hif(acc[0]) + bi0[0]);
                float fg1 = sigm(hif(acc[1]) + bi0[1]);
                float gg1 = tanhf(hif(acc[2]) + bi0[2]);
                float og1 = sigm(hif(acc[3]) + bi0[3]);
                cA1 = fg1 * cA1 + ig1 * gg1;
                float h1v = og1 * tanhf(cA1);
                *reinterpret_cast<float2*>(g_hAT[p] + j * NB + b0) =
                    make_float2(h, h1v);
            }
        }

        grid_barrier(bar_base, bn++);   // hAT[p] complete before layer 1 reads

        // ============ layer 1: gates = [hA_t | hB_prev] @ W1 =============
        {
            u64 acc[4] = {0ull, 0ull, 0ull, 0ull};

            const float* pu = g_hAT[p] + b0;
            #pragma unroll 4
            for (int kk = 0; kk < NH / 2; kk++) {
                u64 h0 = ld64(pu + (2 * kk) * NB);
                u64 h1 = ld64(pu + (2 * kk + 1) * NB);
                #pragma unroll
                for (int g = 0; g < 4; g++) {
                    ulonglong2 w = w1d[g][kk];
                    acc[g] = ffma2(h0, w.x, acc[g]);
                    acc[g] = ffma2(h1, w.y, acc[g]);
                }
            }
            const float* pv = g_hBT[q] + b0;
            #pragma unroll 4
            for (int kk = 0; kk < NH / 2; kk++) {
                u64 h0 = ld64(pv + (2 * kk) * NB);
                u64 h1 = ld64(pv + (2 * kk + 1) * NB);
                #pragma unroll
                for (int g = 0; g < 4; g++) {
                    ulonglong2 w = w1d[g][(NH / 2) + kk];
                    acc[g] = ffma2(h0, w.x, acc[g]);
                    acc[g] = ffma2(h1, w.y, acc[g]);
                }
            }
            {
                float ig = sigm(lof(acc[0]) + bi1[0]);
                float fg = sigm(lof(acc[1]) + bi1[1]);
                float gg = tanhf(lof(acc[2]) + bi1[2]);
                float og = sigm(lof(acc[3]) + bi1[3]);
                cB0 = fg * cB0 + ig * gg;
                float h = og * tanhf(cB0);
                float ig1 = sigm(hif(acc[0]) + bi1[0]);
                float fg1 = sigm(hif(acc[1]) + bi1[1]);
                float gg1 = tanhf(hif(acc[2]) + bi1[2]);
                float og1 = sigm(hif(acc[3]) + bi1[3]);
                cB1 = fg1 * cB1 + ig1 * gg1;
                float h1v = og1 * tanhf(cB1);
                *reinterpret_cast<float2*>(g_hBT[p] + j * NB + b0) =
                    make_float2(h, h1v);
            }
        }
        // No end-of-step barrier (safe: hBT[p] readers sit behind the t+1
        // mid-barrier; hAT[q] writers at t+1 come after all t reads of it).
    }

    grid_barrier(bar_base, bn++);

    // ---- output head: out[b][c] = sum_k hBT_last[k][b] * Wout[c][k] ----
    if (cta == 0) {
        for (int idx = tid; idx < NB * NC; idx += NTHR) {
            int bb = idx / NC, cc = idx - bb * NC;
            const float* hr = g_hBT[(NT - 1) & 1] + bb;
            const float* wr = Wout + cc * NH;
            float s0 = 0.f, s1 = 0.f, s2 = 0.f, s3 = 0.f;
            #pragma unroll 4
            for (int k = 0; k < NH; k += 4) {
                s0 += hr[(k + 0) * NB] * wr[k + 0];
                s1 += hr[(k + 1) * NB] * wr[k + 1];
                s2 += hr[(k + 2) * NB] * wr[k + 2];
                s3 += hr[(k + 3) * NB] * wr[k + 3];
            }
            out[bb * NC + cc] = s0 + s1 + s2 + s3 + bout[cc];
        }
    }
}

extern "C" void kernel_launch(void* const* d_in, const int* in_sizes, int n_in,
                              void* d_out, int out_size) {
    (void)in_sizes; (void)n_in; (void)out_size;
    const float* x    = (const float*)d_in[0];
    const float* Wih0 = (const float*)d_in[1];
    const float* Whh0 = (const float*)d_in[2];
    const float* bih0 = (const float*)d_in[3];
    const float* bhh0 = (const float*)d_in[4];
    const float* Wih1 = (const float*)d_in[5];
    const float* Whh1 = (const float*)d_in[6];
    const float* bih1 = (const float*)d_in[7];
    const float* bhh1 = (const float*)d_in[8];
    const float* Wout = (const float*)d_in[9];
    const float* bout = (const float*)d_in[10];
    float* out = (float*)d_out;

    transpose_x_kernel<<<dim3(NT, NB / 32), 256>>>(x);

    const size_t shbytes = (size_t)(16 * PD0 + 16 * PD1) * sizeof(float); // 205312
    cudaFuncSetAttribute(lstm_persistent,
                         cudaFuncAttributeMaxDynamicSharedMemorySize,
                         (int)shbytes);
    lstm_persistent<<<NCTA, NTHR, shbytes>>>(
        Wih0, Whh0, bih0, bhh0, Wih1, Whh1, bih1, bhh1, Wout, bout, out);
}